// round 5
// baseline (speedup 1.0000x reference)
#include <cuda_runtime.h>
#include <cstdint>

// Problem constants
#define B 32
#define L 6
#define R 8
#define H 64
#define NTRAJ 262144              // R^L
#define F4_PER_B 393216           // NTRAJ * L / 4
#define TRAJ_PER_BLK 4096         // trajectories per expand block
#define F4_PER_BLK   6144
#define CHUNK_TRAJ   512
#define CHUNK_FLOATS 3072         // 512 * 6
#define CHUNK_BYTES  12288
#define CHUNKS       8
#define ITEMS_PER_MLP_BLK 4

__device__ float g_q0[B * L * R];

// ---------------------------------------------------------------------------
// Kernel 1: tiny MLP, 4 items per 256-thread block (unchanged from R4).
// ---------------------------------------------------------------------------
__global__ void __launch_bounds__(256) zdec_mlp_kernel(
    const float* __restrict__ phi, const float* __restrict__ rp,
    const float* __restrict__ W1,  const float* __restrict__ b1,
    const float* __restrict__ W2,  const float* __restrict__ b2,
    const float* __restrict__ W3,  const float* __restrict__ b3)
{
    __shared__ float sW2[H * 65];
    __shared__ float sh1[ITEMS_PER_MLP_BLK][H];
    __shared__ float sred[ITEMS_PER_MLP_BLK][2];

    const int tid  = threadIdx.x;
    const int item = tid >> 6;
    const int j    = tid & 63;

#pragma unroll
    for (int t = tid; t < H * H; t += 256) {
        const int g = t >> 6, k = t & 63;
        sW2[g * 65 + k] = W2[t];
    }

    const int ii = blockIdx.x * ITEMS_PER_MLP_BLK + item;
    const int b  = ii / (L * R);
    const int lr = ii % (L * R);
    const int l  = lr / R;

    const float  x  = rp[lr];
    const float  p  = phi[b * L + l];
    const float2 w1 = reinterpret_cast<const float2*>(W1)[j];

    sh1[item][j] = fmaxf(fmaf(w1.x, x, fmaf(w1.y, p, b1[j])), 0.0f);
    __syncthreads();

    float acc = b2[j];
#pragma unroll
    for (int k = 0; k < H; k++)
        acc = fmaf(sW2[j * 65 + k], sh1[item][k], acc);

    float q = W3[j] * fmaxf(acc, 0.0f);
#pragma unroll
    for (int off = 16; off > 0; off >>= 1)
        q += __shfl_xor_sync(0xffffffffu, q, off);
    if ((j & 31) == 0) sred[item][j >> 5] = q;
    __syncthreads();
    if (j == 0)
        g_q0[ii] = sred[item][0] + sred[item][1] + b3[0];
}

// ---------------------------------------------------------------------------
// Kernel 2: TMA-store expansion.
// Block (bx, b) covers 4096 trajectories = 96 KB, as 8 chunks of 12 KB.
// Digits: d0,d1,d2 depend only on nl = n mod 512 (chunk-local);
//         l=3 value = sq[24 + ((nc>>9)&7)]  (per chunk);
//         l=4,5 values constant per block.
// => all chunks share one SMEM template; only the 512 l=3 words change.
// Stores leave via cp.async.bulk (TMA), double-buffered.
// ---------------------------------------------------------------------------
__global__ void __launch_bounds__(512) zdec_expand_kernel(float* __restrict__ out)
{
    __shared__ __align__(16) float sbuf[2][CHUNK_FLOATS];   // 24 KB
    __shared__ float sq[L * R];

    const int tid = threadIdx.x;
    const int b   = blockIdx.y;
    if (tid < L * R)
        sq[tid] = g_q0[b * (L * R) + tid];
    __syncthreads();

    const int n_blk = blockIdx.x * TRAJ_PER_BLK;
    const float c4 = sq[32 + ((n_blk >> 12) & 7)];
    const float c5 = sq[40 + ((n_blk >> 15) & 7)];

    // --- Build template (both buffers). Thread t<256 handles traj 2t,2t+1
    //     of a chunk = 3 aligned float4s at f4 index 3t.
    if (tid < 256) {
        const int nl = 2 * tid;                 // even local traj
        const int d0 = nl & 7;
        const int d1 = (nl >> 3) & 7;
        const int d2 = (nl >> 6) & 7;
        const float s0 = sq[d0], s0o = sq[d0 + 1];
        const float s1 = sq[8 + d1];
        const float s2 = sq[16 + d2];

        float4 v0 = make_float4(s0, s1, s2, 0.0f);      // l3 slot patched later
        float4 v1 = make_float4(c4, c5, s0o, s1);
        float4 v2 = make_float4(s2, 0.0f, c4, c5);      // l3 slot patched later

        float4* t0 = reinterpret_cast<float4*>(sbuf[0]) + 3 * tid;
        float4* t1 = reinterpret_cast<float4*>(sbuf[1]) + 3 * tid;
        t0[0] = v0; t0[1] = v1; t0[2] = v2;
        t1[0] = v0; t1[1] = v1; t1[2] = v2;
    }
    __syncthreads();

    char* dst_base = reinterpret_cast<char*>(out)
                   + (((size_t)b * F4_PER_B + (size_t)blockIdx.x * F4_PER_BLK) * 16);

#pragma unroll
    for (int ch = 0; ch < CHUNKS; ch++) {
        const int   buf = ch & 1;
        const int   nc  = n_blk + ch * CHUNK_TRAJ;
        const float c3  = sq[24 + ((nc >> 9) & 7)];

        // ensure TMA finished reading this buffer (2 chunks ago)
        if (tid == 0)
            asm volatile("cp.async.bulk.wait_group.read 1;" ::: "memory");
        __syncthreads();

        // patch the 512 l=3 words: float offset 6*t + 3
        sbuf[buf][6 * tid + 3] = c3;

        // make generic-proxy writes visible to async proxy, then launch TMA
        asm volatile("fence.proxy.async.shared::cta;" ::: "memory");
        __syncthreads();

        if (tid == 0) {
            uint32_t saddr;
            asm("{ .reg .u64 t; cvta.to.shared.u64 t, %1; cvt.u32.u64 %0, t; }"
                : "=r"(saddr) : "l"(&sbuf[buf][0]));
            asm volatile(
                "cp.async.bulk.global.shared::cta.bulk_group [%0], [%1], %2;"
                :: "l"(dst_base + (size_t)ch * CHUNK_BYTES), "r"(saddr),
                   "n"(CHUNK_BYTES) : "memory");
            asm volatile("cp.async.bulk.commit_group;" ::: "memory");
        }
    }

    if (tid == 0)
        asm volatile("cp.async.bulk.wait_group 0;" ::: "memory");
}

// ---------------------------------------------------------------------------
extern "C" void kernel_launch(void* const* d_in, const int* in_sizes, int n_in,
                              void* d_out, int out_size)
{
    const float* phi = (const float*)d_in[0];
    const float* rp  = (const float*)d_in[1];
    const float* W1  = (const float*)d_in[2];
    const float* b1  = (const float*)d_in[3];
    const float* W2  = (const float*)d_in[4];
    const float* b2  = (const float*)d_in[5];
    const float* W3  = (const float*)d_in[6];
    const float* b3  = (const float*)d_in[7];
    float* out = (float*)d_out;

    zdec_mlp_kernel<<<(B * L * R) / ITEMS_PER_MLP_BLK, 256>>>(
        phi, rp, W1, b1, W2, b2, W3, b3);

    dim3 grid(NTRAJ / TRAJ_PER_BLK, B);            // (64, 32)
    zdec_expand_kernel<<<grid, 512>>>(out);
}

// round 6
// speedup vs baseline: 1.3856x; 1.3856x over previous
#include <cuda_runtime.h>
#include <cstdint>

// Problem constants
#define B 32
#define L 6
#define R 8
#define H 64
#define NTRAJ 262144              // R^L
#define F4_PER_B 393216           // NTRAJ * L / 4
#define TRAJ_PER_BLK 8192
#define F4_PER_BLK   12288        // TRAJ_PER_BLK*6/4
#define SUB_TRAJ     2048         // trajectories per sub-tile
#define SUB_F4       3072         // 48 KB
#define SUB_BYTES    49152
#define NSUB         4
#define ITEMS_PER_MLP_BLK 4

__device__ float g_q0[B * L * R];

// ---------------------------------------------------------------------------
// Kernel 1: tiny MLP, 4 items per 256-thread block (unchanged).
// ---------------------------------------------------------------------------
__global__ void __launch_bounds__(256) zdec_mlp_kernel(
    const float* __restrict__ phi, const float* __restrict__ rp,
    const float* __restrict__ W1,  const float* __restrict__ b1,
    const float* __restrict__ W2,  const float* __restrict__ b2,
    const float* __restrict__ W3,  const float* __restrict__ b3)
{
    __shared__ float sW2[H * 65];
    __shared__ float sh1[ITEMS_PER_MLP_BLK][H];
    __shared__ float sred[ITEMS_PER_MLP_BLK][2];

    const int tid  = threadIdx.x;
    const int item = tid >> 6;
    const int j    = tid & 63;

#pragma unroll
    for (int t = tid; t < H * H; t += 256) {
        const int g = t >> 6, k = t & 63;
        sW2[g * 65 + k] = W2[t];
    }

    const int ii = blockIdx.x * ITEMS_PER_MLP_BLK + item;
    const int b  = ii / (L * R);
    const int lr = ii % (L * R);
    const int l  = lr / R;

    const float  x  = rp[lr];
    const float  p  = phi[b * L + l];
    const float2 w1 = reinterpret_cast<const float2*>(W1)[j];

    sh1[item][j] = fmaxf(fmaf(w1.x, x, fmaf(w1.y, p, b1[j])), 0.0f);
    __syncthreads();

    float acc = b2[j];
#pragma unroll
    for (int k = 0; k < H; k++)
        acc = fmaf(sW2[j * 65 + k], sh1[item][k], acc);

    float q = W3[j] * fmaxf(acc, 0.0f);
#pragma unroll
    for (int off = 16; off > 0; off >>= 1)
        q += __shfl_xor_sync(0xffffffffu, q, off);
    if ((j & 31) == 0) sred[item][j >> 5] = q;
    __syncthreads();
    if (j == 0)
        g_q0[ii] = sred[item][0] + sred[item][1] + b3[0];
}

// ---------------------------------------------------------------------------
// Kernel 2: pipelined TMA-store expansion.
// Block (bx, b): 8192 trajectories = 192 KB, as 4 sub-tiles of 48 KB,
// double-buffered (2 x 12288 floats, dynamic SMEM). Each thread builds
// 2 units (2 trajectories each = 3 aligned float4s) per sub-tile, then one
// thread issues a single 48 KB cp.async.bulk. wait_group.read 1 => depth-2.
// ---------------------------------------------------------------------------
extern __shared__ float es[];

__global__ void __launch_bounds__(512) zdec_expand_kernel(float* __restrict__ out)
{
    float* buf[2] = { es, es + SUB_F4 * 4 };
    float* sq     = es + 2 * SUB_F4 * 4;

    const int tid = threadIdx.x;
    const int b   = blockIdx.y;
    if (tid < L * R)
        sq[tid] = g_q0[b * (L * R) + tid];
    __syncthreads();

    const int n_blk = blockIdx.x * TRAJ_PER_BLK;
    char* dst_base = reinterpret_cast<char*>(out)
                   + (((size_t)b * F4_PER_B + (size_t)blockIdx.x * F4_PER_BLK) * 16);

#pragma unroll
    for (int st = 0; st < NSUB; st++) {
        float* sb = buf[st & 1];

        // make sure the copy issued 2 sub-tiles ago has finished READING sb
        if (st >= 2) {
            if (tid == 0)
                asm volatile("cp.async.bulk.wait_group.read 1;" ::: "memory");
            __syncthreads();
        }

        // build 48 KB sub-tile: units u = tid, tid+512; unit u = trajs 2u,2u+1
#pragma unroll
        for (int uu = 0; uu < 2; uu++) {
            const int u  = uu * 512 + tid;
            const int n  = n_blk + st * SUB_TRAJ + 2 * u;   // even
            const int d0 = n & 7;
            const float s0  = sq[d0];
            const float s0o = sq[d0 + 1];
            const float s1  = sq[ 8 + ((n >> 3)  & 7)];
            const float s2  = sq[16 + ((n >> 6)  & 7)];
            const float s3  = sq[24 + ((n >> 9)  & 7)];
            const float s4  = sq[32 + ((n >> 12) & 7)];
            const float s5  = sq[40 + ((n >> 15) & 7)];

            float4* t4 = reinterpret_cast<float4*>(sb) + 3 * u;
            t4[0] = make_float4(s0, s1, s2, s3);
            t4[1] = make_float4(s4, s5, s0o, s1);
            t4[2] = make_float4(s2, s3, s4, s5);
        }

        asm volatile("fence.proxy.async.shared::cta;" ::: "memory");
        __syncthreads();

        if (tid == 0) {
            uint32_t saddr;
            asm("{ .reg .u64 t; cvta.to.shared.u64 t, %1; cvt.u32.u64 %0, t; }"
                : "=r"(saddr) : "l"(sb));
            asm volatile(
                "cp.async.bulk.global.shared::cta.bulk_group [%0], [%1], %2;"
                :: "l"(dst_base + (size_t)st * SUB_BYTES), "r"(saddr),
                   "n"(SUB_BYTES) : "memory");
            asm volatile("cp.async.bulk.commit_group;" ::: "memory");
        }
    }

    // block may not exit while TMA still reads its SMEM
    if (tid == 0)
        asm volatile("cp.async.bulk.wait_group.read 0;" ::: "memory");
    __syncthreads();
}

// ---------------------------------------------------------------------------
extern "C" void kernel_launch(void* const* d_in, const int* in_sizes, int n_in,
                              void* d_out, int out_size)
{
    const float* phi = (const float*)d_in[0];
    const float* rp  = (const float*)d_in[1];
    const float* W1  = (const float*)d_in[2];
    const float* b1  = (const float*)d_in[3];
    const float* W2  = (const float*)d_in[4];
    const float* b2  = (const float*)d_in[5];
    const float* W3  = (const float*)d_in[6];
    const float* b3  = (const float*)d_in[7];
    float* out = (float*)d_out;

    static bool attr_set = false;
    const int smem_bytes = 2 * SUB_BYTES + 256;    // 96 KB bufs + sq
    if (!attr_set) {
        cudaFuncSetAttribute(zdec_expand_kernel,
                             cudaFuncAttributeMaxDynamicSharedMemorySize,
                             smem_bytes);
        attr_set = true;
    }

    zdec_mlp_kernel<<<(B * L * R) / ITEMS_PER_MLP_BLK, 256>>>(
        phi, rp, W1, b1, W2, b2, W3, b3);

    dim3 grid(NTRAJ / TRAJ_PER_BLK, B);            // (32, 32)
    zdec_expand_kernel<<<grid, 512, smem_bytes>>>(out);
}